// round 14
// baseline (speedup 1.0000x reference)
#include <cuda_runtime.h>
#include <cuda_bf16.h>
#include <cuda_fp16.h>
#include <math.h>

#define Bdim 2
#define Sdim 2048
#define Ddim 1024
#define Hdim 16
#define DHdim 64
#define NROWS (Bdim * Sdim)   // 4096
#define NROWS_A (32 * Sdim)   // 65536
#define PLANE ((size_t)NROWS * Ddim)  // 4M elems

typedef unsigned short ushortT;

// ---- persistent fp16 planes (allocation-free contract) ----
__device__ ushortT g_inh[3 * PLANE];                       // fp16 qs/ks/vs (hi only)
__device__ ushortT g_qkvh[3 * PLANE];                      // projected q/k/v hi
__device__ ushortT g_vth[32 * DHdim * Sdim];               // V^T hi plane
__device__ ushortT g_wh[4 * Ddim * Ddim];                  // W^T [n][k] hi plane
__device__ ushortT g_ch[PLANE], g_cl[PLANE];               // ctx split planes
__device__ ushortT g_exph[(size_t)NROWS_A * Sdim];         // fp16 exp scratch
__device__ float g_bias[3 * Ddim];
__device__ float g_part[(size_t)NROWS_A * 16];
__device__ float g_inv[NROWS_A];
__device__ int   g_mask[NROWS];

// ---------------------------------------------------------------------------
__global__ void mask_expand_kernel(const void* __restrict__ mraw,
                                   const float* __restrict__ bq,
                                   const float* __restrict__ bk,
                                   const float* __restrict__ bv) {
    __shared__ int smode;
    if (threadIdx.x == 0) {
        const unsigned* w = (const unsigned*)mraw;
        int any_gt1 = 0, all_float = 1;
        for (int i = 0; i < 1024; ++i) {
            unsigned v = w[i];
            if (v > 1u) any_gt1 = 1;
            if (v != 0u && v != 0x3F800000u) all_float = 0;
        }
        smode = any_gt1 ? (all_float ? 2 : 1) : 0;  // 0=int32, 1=byte, 2=float
    }
    __syncthreads();
    int mode = smode;
    for (int i = threadIdx.x; i < NROWS; i += blockDim.x) {
        int v;
        if (mode == 1)      v = ((const unsigned char*)mraw)[i] != 0;
        else if (mode == 2) v = ((const float*)mraw)[i] != 0.0f;
        else                v = ((const int*)mraw)[i] != 0;
        g_mask[i] = v;
    }
    for (int i = threadIdx.x; i < Ddim; i += blockDim.x) {
        g_bias[i]            = bq[i];
        g_bias[Ddim + i]     = bk[i];
        g_bias[2 * Ddim + i] = bv[i];
    }
}

// ---------------------------------------------------------------------------
__device__ __forceinline__ void split_hf(float x, ushortT& h, ushortT& l) {
    __half hh = __float2half_rn(x);
    float r = x - __half2float(hh);
    __half ll = __float2half_rn(r);
    h = __half_as_ushort(hh);
    l = __half_as_ushort(ll);
}
__device__ __forceinline__ void ldmx4(unsigned (&r)[4], unsigned addr) {
    asm volatile("ldmatrix.sync.aligned.m8n8.x4.shared.b16 {%0,%1,%2,%3}, [%4];"
                 : "=r"(r[0]), "=r"(r[1]), "=r"(r[2]), "=r"(r[3]) : "r"(addr));
}
__device__ __forceinline__ void mma_f16(float (&c)[4], const unsigned (&a)[4],
                                        const unsigned b0, const unsigned b1) {
    asm volatile(
        "mma.sync.aligned.m16n8k16.row.col.f32.f16.f16.f32 "
        "{%0,%1,%2,%3}, {%4,%5,%6,%7}, {%8,%9}, {%0,%1,%2,%3};\n"
        : "+f"(c[0]), "+f"(c[1]), "+f"(c[2]), "+f"(c[3])
        : "r"(a[0]), "r"(a[1]), "r"(a[2]), "r"(a[3]), "r"(b0), "r"(b1));
}
__device__ __forceinline__ void cpasync16(unsigned s, const void* g) {
    asm volatile("cp.async.ca.shared.global [%0], [%1], 16;" :: "r"(s), "l"(g));
}
__device__ __forceinline__ void cpcommit() { asm volatile("cp.async.commit_group;"); }
template <int N>
__device__ __forceinline__ void cpwait() {
    asm volatile("cp.async.wait_group %0;" :: "n"(N) : "memory");
}

// ---------------------------------------------------------------------------
// prep kernels
// ---------------------------------------------------------------------------
__global__ __launch_bounds__(256) void split_inputs_kernel(
    const float* __restrict__ q, const float* __restrict__ k, const float* __restrict__ v) {
    const float* src = blockIdx.z == 0 ? q : blockIdx.z == 1 ? k : v;
    ushortT* dh = g_inh + (size_t)blockIdx.z * PLANE;
    size_t i = ((size_t)blockIdx.x * blockDim.x + threadIdx.x) * 4;
    float4 val = *reinterpret_cast<const float4*>(&src[i]);
    ushortT h[4];
    h[0] = __half_as_ushort(__float2half_rn(val.x));
    h[1] = __half_as_ushort(__float2half_rn(val.y));
    h[2] = __half_as_ushort(__float2half_rn(val.z));
    h[3] = __half_as_ushort(__float2half_rn(val.w));
    *reinterpret_cast<uint2*>(&dh[i]) = *reinterpret_cast<uint2*>(h);
}

__global__ __launch_bounds__(256) void wtrans_kernel(
    const float* __restrict__ w0, const float* __restrict__ w1,
    const float* __restrict__ w2, const float* __restrict__ w3) {
    const float* W = blockIdx.z == 0 ? w0 : blockIdx.z == 1 ? w1 : blockIdx.z == 2 ? w2 : w3;
    ushortT* Th = g_wh + (size_t)blockIdx.z * Ddim * Ddim;
    __shared__ float tile[32][33];
    const int n0 = blockIdx.x * 32, k0 = blockIdx.y * 32;
    const int tx = threadIdx.x & 31, ty = threadIdx.x >> 5;
#pragma unroll
    for (int r = 0; r < 4; ++r)
        tile[ty + r * 8][tx] = W[(size_t)(k0 + ty + r * 8) * Ddim + n0 + tx];
    __syncthreads();
#pragma unroll
    for (int r = 0; r < 4; ++r) {
        float v = tile[tx][ty + r * 8];
        Th[(size_t)(n0 + ty + r * 8) * Ddim + k0 + tx] =
            __half_as_ushort(__float2half_rn(v));
    }
}

__global__ __launch_bounds__(256) void vtrans_kernel() {
    const int bh = blockIdx.z, b = bh >> 4, h = bh & 15;
    const int s0 = blockIdx.x * 32, d0 = blockIdx.y * 32;
    __shared__ ushortT th[32][34];
    const int tx = threadIdx.x & 31, ty = threadIdx.x >> 5;
    const ushortT* vh = g_qkvh + 2 * PLANE;
#pragma unroll
    for (int r = 0; r < 4; ++r) {
        size_t src = (size_t)(b * Sdim + s0 + ty + r * 8) * Ddim + h * DHdim + d0 + tx;
        th[ty + r * 8][tx] = vh[src];
    }
    __syncthreads();
#pragma unroll
    for (int r = 0; r < 4; ++r) {
        size_t dst = ((size_t)bh * DHdim + d0 + ty + r * 8) * Sdim + s0 + tx;
        g_vth[dst] = th[tx][ty + r * 8];
    }
}

__global__ __launch_bounds__(256) void rowsum_kernel() {
    const int idx = blockIdx.x * 256 + threadIdx.x;
    float s = 0.0f;
#pragma unroll
    for (int i = 0; i < 16; ++i) s += g_part[(size_t)idx * 16 + i];
    g_inv[idx] = 1.0f / s;
}

// ---------------------------------------------------------------------------
// fp16-split tensor-core GEMM. BM=128 fixed. B always hi-plane only.
// APASS: 2 = A split h+l (2 MMA passes); 1 = A hi only (1 pass).
// ASRC:  0 = fp16 planes via cp.async
//        2 = ctx: A = fp16 exp scratch; scale by g_inv, write fp32 attn out,
//            scaled fp16 into smem (double-buffered), 1 MMA pass.
// EPI:   0 = +bias -> hi plane; 1 = exp/mask (fp16-rounded) -> exp plane +
//        row partial sums of the ROUNDED values; 2 = split h+l planes;
//        3 = +bias -> fp32
// ---------------------------------------------------------------------------
template <int BN, int BKt, int STAGES, int ASRC, int EPI, int APASS>
__global__ __launch_bounds__(256, 2) void mm_kernel(
    const ushortT* __restrict__ Ahp, const ushortT* __restrict__ Alp,
    float* __restrict__ Awb,
    const ushortT* __restrict__ Bhp,
    float* __restrict__ Cf, ushortT* __restrict__ Ch, ushortT* __restrict__ Cl,
    const float* __restrict__ bias,
    int nt, int lda, int ldb, int ldc,
    long sbA, long shA, long sbB, long shB, long sbC, long shC, long sBias) {
    constexpr int KP  = BKt + 8;
    constexpr int APB = 128 * KP * 2;
    constexpr int BPB = BN * KP * 2;
    constexpr int ABUF = 2;
    constexpr int CPR = BKt / 8;
    constexpr int ACH = CPR / 2;
    constexpr int BCH = BN * CPR / 256;
    constexpr int KS  = BKt / 16;
    constexpr int NW  = BN / 32;
    constexpr int N8  = BN / 16;
    constexpr int oAl = ABUF * APB;              // lo buffers (only if APASS==2)
    constexpr int oBh = APASS * ABUF * APB;
    constexpr int WAITN = (STAGES >= 2) ? STAGES - 2 : 0;

    extern __shared__ char smem[];
    const unsigned sbase = (unsigned)__cvta_generic_to_shared(smem);
    float* rsum2 = (float*)(smem + oBh + STAGES * BPB);

    const int t = threadIdx.x, lane = t & 31, warp = t >> 5;
    const int wm = (warp >> 1) * 32, wn = (warp & 1) * (BN / 2);
    const int z = blockIdx.z;
    const long aoff = (long)(z / Hdim) * sbA + (long)(z % Hdim) * shA;
    const long boff = (long)(z / Hdim) * sbB + (long)(z % Hdim) * shB;
    const long coff = (long)(z / Hdim) * sbC + (long)(z % Hdim) * shC;
    bias += (long)(z % Hdim) * sBias;
    const int row0 = blockIdx.y * 128, col0 = blockIdx.x * BN;
    const int lr = lane & 7, lhi = (lane >> 3) & 1, lk = lane >> 4;

    float acc[2][N8][4] = {};

    auto issueA = [&](int s, int kk) {
#pragma unroll
        for (int j = 0; j < ACH; ++j) {
            const int o = j * 256 + t, r = o / CPR, c = o % CPR;
            const unsigned d = sbase + s * APB + (unsigned)(r * KP + c * 8) * 2;
            const size_t g = aoff + (size_t)(row0 + r) * lda + kk + c * 8;
            cpasync16(d, &Ahp[g]);
            if (APASS == 2) cpasync16(d + oAl, &Alp[g]);
        }
    };
    auto issueB = [&](int s, int kk) {
#pragma unroll
        for (int j = 0; j < BCH; ++j) {
            const int o = j * 256 + t, r = o / CPR, c = o % CPR;
            const unsigned d = sbase + oBh + s * BPB + (unsigned)(r * KP + c * 8) * 2;
            const size_t g = boff + (size_t)(col0 + r) * ldb + kk + c * 8;
            cpasync16(d, &Bhp[g]);
        }
    };
    auto compute = [&](int sA, int sB) {
#pragma unroll
        for (int ks = 0; ks < KS; ++ks) {
            unsigned ah[2][4], al[2][4];
#pragma unroll
            for (int mi = 0; mi < 2; ++mi) {
                const unsigned ad = sbase + sA * APB +
                    (unsigned)((wm + mi * 16 + lr + lhi * 8) * KP + ks * 16 + lk * 8) * 2;
                ldmx4(ah[mi], ad);
                if (APASS == 2) ldmx4(al[mi], ad + oAl);
            }
#pragma unroll
            for (int ni = 0; ni < NW; ++ni) {
                const unsigned bd = sbase + oBh + sB * BPB +
                    (unsigned)((wn + ni * 16 + lr + lhi * 8) * KP + ks * 16 + lk * 8) * 2;
                unsigned rh[4];
                ldmx4(rh, bd);
#pragma unroll
                for (int mi = 0; mi < 2; ++mi) {
                    mma_f16(acc[mi][ni * 2],     ah[mi], rh[0], rh[2]);
                    mma_f16(acc[mi][ni * 2 + 1], ah[mi], rh[1], rh[3]);
                    if (APASS == 2) {
                        mma_f16(acc[mi][ni * 2],     al[mi], rh[0], rh[2]);
                        mma_f16(acc[mi][ni * 2 + 1], al[mi], rh[1], rh[3]);
                    }
                }
            }
        }
    };

    if (ASRC == 0) {
        if (STAGES == 1) {
            for (int i = 0; i < nt; ++i) {
                if (i > 0) __syncthreads();
                issueA(0, i * BKt); issueB(0, i * BKt); cpcommit();
                cpwait<0>();
                __syncthreads();
                compute(0, 0);
            }
        } else {
#pragma unroll 1
            for (int s = 0; s < STAGES - 1 && s < nt; ++s) {
                issueA(s, s * BKt); issueB(s, s * BKt); cpcommit();
            }
            for (int i = 0; i < nt; ++i) {
                cpwait<WAITN>();
                __syncthreads();
                const int nx = i + STAGES - 1;
                if (nx < nt) { issueA(nx % STAGES, nx * BKt); issueB(nx % STAGES, nx * BKt); }
                cpcommit();
                compute(i % STAGES, i % STAGES);
            }
        }
    } else {
        // ctx path: A = fp16 exp scratch. Per tile: scale by inv, write fp32
        // attn out, scaled fp16 into double-buffered smem. EPT = elems/thread.
        constexpr int EPT = BKt / 2;
        const int ar = t >> 1, ac0 = (t & 1) * EPT;
        const float invv = g_inv[(size_t)z * Sdim + row0 + ar];
        const size_t arow = aoff + (size_t)(row0 + ar) * lda;
        uint4 areg[EPT / 8];
#pragma unroll
        for (int j = 0; j < EPT / 8; ++j)
            areg[j] = *reinterpret_cast<const uint4*>(&Ahp[arow + ac0 + j * 8]);
        issueB(0, 0); cpcommit();
        for (int i = 0; i < nt; ++i) {
            const int sA = i & 1;
            const size_t cbase = arow + (size_t)i * BKt + ac0;
            float fv[EPT];
            ushortT hs[EPT];
            const ushortT* ap = reinterpret_cast<const ushortT*>(areg);
#pragma unroll
            for (int j = 0; j < EPT; ++j) {
                float e = __half2float(__ushort_as_half(ap[j])) * invv;
                fv[j] = e;
                hs[j] = __half_as_ushort(__float2half_rn(e));
            }
#pragma unroll
            for (int j4 = 0; j4 < EPT / 4; ++j4)
                *reinterpret_cast<float4*>(&Awb[cbase + j4 * 4]) =
                    make_float4(fv[j4 * 4], fv[j4 * 4 + 1], fv[j4 * 4 + 2], fv[j4 * 4 + 3]);
            const unsigned off = (unsigned)(sA * APB + (ar * KP + ac0) * 2);
#pragma unroll
            for (int j = 0; j < EPT / 8; ++j)
                *reinterpret_cast<uint4*>(smem + off + j * 16) =
                    *reinterpret_cast<uint4*>(&hs[j * 8]);
            if (i + 1 < nt) {
#pragma unroll
                for (int j = 0; j < EPT / 8; ++j)
                    areg[j] = *reinterpret_cast<const uint4*>(
                        &Ahp[arow + (size_t)(i + 1) * BKt + ac0 + j * 8]);
            }
            cpwait<0>();      // B(i) arrived
            __syncthreads();  // A STS visible; everyone done with compute(i-1)
            if (i + 1 < nt) { issueB((i + 1) & 1, (i + 1) * BKt); cpcommit(); }
            compute(sA, i & 1);
        }
    }

    // ---- epilogue ----
    const int maskbase = (z / Hdim) * Sdim;
#pragma unroll
    for (int mi = 0; mi < 2; ++mi)
#pragma unroll
        for (int n8 = 0; n8 < N8; ++n8) {
            const int rl0 = wm + mi * 16 + (lane >> 2);
            const int cl0 = wn + n8 * 8 + (lane & 3) * 2;
#pragma unroll
            for (int hf = 0; hf < 2; ++hf) {
                const int r = row0 + rl0 + hf * 8;
                const int c = col0 + cl0;
                float v0 = acc[mi][n8][hf * 2], v1 = acc[mi][n8][hf * 2 + 1];
                if (EPI == 0 || EPI == 3) { v0 += bias[c]; v1 += bias[c + 1]; }
                const size_t ci = coff + (size_t)r * ldc + c;
                if (EPI == 1) {
                    v0 = g_mask[maskbase + c]     ? __expf(v0 * 0.125f) : 0.0f;
                    v1 = g_mask[maskbase + c + 1] ? __expf(v1 * 0.125f) : 0.0f;
                    ushortT h0 = __half_as_ushort(__float2half_rn(v0));
                    ushortT h1 = __half_as_ushort(__float2half_rn(v1));
                    v0 = __half2float(__ushort_as_half(h0));   // rounded values
                    v1 = __half2float(__ushort_as_half(h1));   // for exact rowsum
                    acc[mi][n8][hf * 2] = v0; acc[mi][n8][hf * 2 + 1] = v1;
                    *reinterpret_cast<unsigned*>(&Ch[ci]) = (unsigned)h0 | ((unsigned)h1 << 16);
                } else if (EPI == 3) {
                    *reinterpret_cast<float2*>(&Cf[ci]) = make_float2(v0, v1);
                } else if (EPI == 0) {
                    ushortT h0 = __half_as_ushort(__float2half_rn(v0));
                    ushortT h1 = __half_as_ushort(__float2half_rn(v1));
                    *reinterpret_cast<unsigned*>(&Ch[ci]) = (unsigned)h0 | ((unsigned)h1 << 16);
                } else {  // EPI == 2: split planes for outproj
                    ushortT h0, l0, h1, l1;
                    split_hf(v0, h0, l0); split_hf(v1, h1, l1);
                    *reinterpret_cast<unsigned*>(&Ch[ci]) = (unsigned)h0 | ((unsigned)h1 << 16);
                    *reinterpret_cast<unsigned*>(&Cl[ci]) = (unsigned)l0 | ((unsigned)l1 << 16);
                }
            }
        }

    if (EPI == 1) {
#pragma unroll
        for (int mi = 0; mi < 2; ++mi)
#pragma unroll
            for (int hf = 0; hf < 2; ++hf) {
                float s = 0.0f;
#pragma unroll
                for (int n8 = 0; n8 < N8; ++n8)
                    s += acc[mi][n8][hf * 2] + acc[mi][n8][hf * 2 + 1];
                s += __shfl_xor_sync(0xFFFFFFFFu, s, 1);
                s += __shfl_xor_sync(0xFFFFFFFFu, s, 2);
                if ((lane & 3) == 0)
                    rsum2[(warp & 1) * 128 + wm + mi * 16 + (lane >> 2) + hf * 8] = s;
            }
        __syncthreads();
        if (t < 128) {
            float s = rsum2[t] + rsum2[128 + t];
            g_part[((size_t)z * Sdim + row0 + t) * 16 + blockIdx.x] = s;
        }
    }
}

// ---------------------------------------------------------------------------
extern "C" void kernel_launch(void* const* d_in, const int* in_sizes, int n_in,
                              void* d_out, int out_size) {
    const float* qs = (const float*)d_in[0];
    const float* ks = (const float*)d_in[1];
    const float* vs = (const float*)d_in[2];
    const void*  mk = d_in[3];
    const float* Wq = (const float*)d_in[4];
    const float* bq = (const float*)d_in[5];
    const float* Wk = (const float*)d_in[6];
    const float* bk = (const float*)d_in[7];
    const float* Wv = (const float*)d_in[8];
    const float* bv = (const float*)d_in[9];
    const float* Wo = (const float*)d_in[10];
    const float* bo = (const float*)d_in[11];

    float* out  = (float*)d_out;
    float* attn = out + PLANE;  // (out, attn) concatenated

    ushortT *inh, *qkvh, *vth, *wh, *ch, *cl, *exph;
    float* dbias;
    cudaGetSymbolAddress((void**)&inh,  g_inh);
    cudaGetSymbolAddress((void**)&qkvh, g_qkvh);
    cudaGetSymbolAddress((void**)&vth,  g_vth);
    cudaGetSymbolAddress((void**)&wh,   g_wh);
    cudaGetSymbolAddress((void**)&ch,   g_ch);   cudaGetSymbolAddress((void**)&cl,   g_cl);
    cudaGetSymbolAddress((void**)&exph, g_exph);
    cudaGetSymbolAddress((void**)&dbias, g_bias);

    const long SS = (long)Sdim * Sdim;
    const long SD = (long)Sdim * Ddim;
    const size_t WSZ = (size_t)Ddim * Ddim;
    dim3 blk(256);

    // smem: APASS*ABUF*APB + STAGES*BPB (+1024 rsum when EPI==1)
    const int SM_QKV  = 2 * (128 * 72 * 2) + 2 * (128 * 72 * 2);           // 73728 (BK=64)
    const int SM_SC   = 2 * (128 * 72 * 2) + 1 * (128 * 72 * 2) + 1024;    // 56320
    const int SM_CTX  = 2 * (128 * 72 * 2) + 2 * (64 * 72 * 2);            // 55296 (BK=64)
    const int SM_OUT  = 4 * (128 * 40 * 2) + 2 * (128 * 40 * 2);           // 61440 (BK=32)
    cudaFuncSetAttribute(mm_kernel<128, 64, 2, 0, 0, 1>, cudaFuncAttributeMaxDynamicSharedMemorySize, SM_QKV);
    cudaFuncSetAttribute(mm_kernel<128, 64, 1, 0, 1, 1>, cudaFuncAttributeMaxDynamicSharedMemorySize, SM_SC);
    cudaFuncSetAttribute(mm_kernel<64, 64, 2, 2, 2, 1>,  cudaFuncAttributeMaxDynamicSharedMemorySize, SM_CTX);
    cudaFuncSetAttribute(mm_kernel<128, 32, 2, 0, 3, 2>, cudaFuncAttributeMaxDynamicSharedMemorySize, SM_OUT);

    mask_expand_kernel<<<1, 256>>>(mk, bq, bk, bv);
    split_inputs_kernel<<<dim3(4096, 1, 3), blk>>>(qs, ks, vs);
    wtrans_kernel<<<dim3(32, 32, 4), blk>>>(Wq, Wk, Wv, Wo);

    // Fused QKV projections (1-pass, BK=64) -> q/k/v hi planes
    dim3 gqkv(Ddim / 128, NROWS / 128, 3);  // (8, 32, 3)
    mm_kernel<128, 64, 2, 0, 0, 1><<<gqkv, blk, SM_QKV>>>(
        inh, nullptr, nullptr, wh,
        nullptr, qkvh, nullptr, dbias, 16, Ddim, Ddim, Ddim,
        0, (long)PLANE, 0, (long)WSZ, 0, (long)PLANE, Ddim);

    vtrans_kernel<<<dim3(Sdim / 32, DHdim / 32, 32), blk>>>();

    // scores (1-pass) -> fp16 exp scratch + row partial sums of rounded exps
    dim3 gsc(Sdim / 128, Sdim / 128, Bdim * Hdim);  // (16, 16, 32)
    mm_kernel<128, 64, 1, 0, 1, 1><<<gsc, blk, SM_SC>>>(
        qkvh, nullptr, nullptr, qkvh + PLANE,
        nullptr, exph, nullptr, nullptr,
        1, Ddim, Ddim, Sdim, SD, DHdim, SD, DHdim, 16 * SS, SS, 0);

    rowsum_kernel<<<NROWS_A / 256, 256>>>();

    // ctx (1-pass, BK=64, A=fp16 exp scratch): fp32 attn out + ctx planes
    dim3 gctx(1, Sdim / 128, Bdim * Hdim);  // (1, 16, 32)
    mm_kernel<64, 64, 2, 2, 2, 1><<<gctx, blk, SM_CTX>>>(
        exph, nullptr, attn, vth, nullptr, ch, cl, nullptr,
        32, Sdim, Sdim, Ddim,
        16 * SS, SS, (long)16 * DHdim * Sdim, (long)DHdim * Sdim, SD, DHdim, 0);

    // output projection (A=ctx split 2-pass, BK=32) -> fp32 out
    dim3 gproj(Ddim / 128, NROWS / 128, 1);  // (8, 32)
    mm_kernel<128, 32, 2, 0, 3, 2><<<gproj, blk, SM_OUT>>>(
        ch, cl, nullptr, wh + 3 * WSZ,
        out, nullptr, nullptr, bo, 32, Ddim, Ddim, Ddim, 0, 0, 0, 0, 0, 0, 0);
}

// round 15
// speedup vs baseline: 1.0492x; 1.0492x over previous
#include <cuda_runtime.h>
#include <cuda_bf16.h>
#include <cuda_fp16.h>
#include <math.h>

#define Bdim 2
#define Sdim 2048
#define Ddim 1024
#define Hdim 16
#define DHdim 64
#define NROWS (Bdim * Sdim)   // 4096
#define NROWS_A (32 * Sdim)   // 65536
#define PLANE ((size_t)NROWS * Ddim)  // 4M elems

typedef unsigned short ushortT;

// ---- persistent fp16 planes (allocation-free contract) ----
__device__ ushortT g_inh[3 * PLANE];                       // fp16 qs/ks/vs (hi only)
__device__ ushortT g_qkvh[3 * PLANE];                      // projected q/k/v hi
__device__ ushortT g_vth[32 * DHdim * Sdim];               // V^T hi plane
__device__ ushortT g_wh[4 * Ddim * Ddim];                  // W^T [n][k] hi plane
__device__ ushortT g_ch[PLANE], g_cl[PLANE];               // ctx split planes
__device__ ushortT g_exph[(size_t)NROWS_A * Sdim];         // fp16 exp scratch
__device__ float g_bias[3 * Ddim];
__device__ float g_part[(size_t)NROWS_A * 16];
__device__ float g_inv[NROWS_A];
__device__ int   g_mask[NROWS];

// ---------------------------------------------------------------------------
__global__ void mask_expand_kernel(const void* __restrict__ mraw,
                                   const float* __restrict__ bq,
                                   const float* __restrict__ bk,
                                   const float* __restrict__ bv) {
    __shared__ int smode;
    if (threadIdx.x == 0) {
        const unsigned* w = (const unsigned*)mraw;
        int any_gt1 = 0, all_float = 1;
        for (int i = 0; i < 1024; ++i) {
            unsigned v = w[i];
            if (v > 1u) any_gt1 = 1;
            if (v != 0u && v != 0x3F800000u) all_float = 0;
        }
        smode = any_gt1 ? (all_float ? 2 : 1) : 0;  // 0=int32, 1=byte, 2=float
    }
    __syncthreads();
    int mode = smode;
    for (int i = threadIdx.x; i < NROWS; i += blockDim.x) {
        int v;
        if (mode == 1)      v = ((const unsigned char*)mraw)[i] != 0;
        else if (mode == 2) v = ((const float*)mraw)[i] != 0.0f;
        else                v = ((const int*)mraw)[i] != 0;
        g_mask[i] = v;
    }
    for (int i = threadIdx.x; i < Ddim; i += blockDim.x) {
        g_bias[i]            = bq[i];
        g_bias[Ddim + i]     = bk[i];
        g_bias[2 * Ddim + i] = bv[i];
    }
}

// ---------------------------------------------------------------------------
__device__ __forceinline__ void split_hf(float x, ushortT& h, ushortT& l) {
    __half hh = __float2half_rn(x);
    float r = x - __half2float(hh);
    __half ll = __float2half_rn(r);
    h = __half_as_ushort(hh);
    l = __half_as_ushort(ll);
}
__device__ __forceinline__ void ldmx4(unsigned (&r)[4], unsigned addr) {
    asm volatile("ldmatrix.sync.aligned.m8n8.x4.shared.b16 {%0,%1,%2,%3}, [%4];"
                 : "=r"(r[0]), "=r"(r[1]), "=r"(r[2]), "=r"(r[3]) : "r"(addr));
}
__device__ __forceinline__ void mma_f16(float (&c)[4], const unsigned (&a)[4],
                                        const unsigned b0, const unsigned b1) {
    asm volatile(
        "mma.sync.aligned.m16n8k16.row.col.f32.f16.f16.f32 "
        "{%0,%1,%2,%3}, {%4,%5,%6,%7}, {%8,%9}, {%0,%1,%2,%3};\n"
        : "+f"(c[0]), "+f"(c[1]), "+f"(c[2]), "+f"(c[3])
        : "r"(a[0]), "r"(a[1]), "r"(a[2]), "r"(a[3]), "r"(b0), "r"(b1));
}
__device__ __forceinline__ void cpasync16(unsigned s, const void* g) {
    asm volatile("cp.async.ca.shared.global [%0], [%1], 16;" :: "r"(s), "l"(g));
}
__device__ __forceinline__ void cpcommit() { asm volatile("cp.async.commit_group;"); }
template <int N>
__device__ __forceinline__ void cpwait() {
    asm volatile("cp.async.wait_group %0;" :: "n"(N) : "memory");
}

// ---------------------------------------------------------------------------
// prep kernels
// ---------------------------------------------------------------------------
__global__ __launch_bounds__(256) void split_inputs_kernel(
    const float* __restrict__ q, const float* __restrict__ k, const float* __restrict__ v) {
    const float* src = blockIdx.z == 0 ? q : blockIdx.z == 1 ? k : v;
    ushortT* dh = g_inh + (size_t)blockIdx.z * PLANE;
    size_t i = ((size_t)blockIdx.x * blockDim.x + threadIdx.x) * 4;
    float4 val = *reinterpret_cast<const float4*>(&src[i]);
    ushortT h[4];
    h[0] = __half_as_ushort(__float2half_rn(val.x));
    h[1] = __half_as_ushort(__float2half_rn(val.y));
    h[2] = __half_as_ushort(__float2half_rn(val.z));
    h[3] = __half_as_ushort(__float2half_rn(val.w));
    *reinterpret_cast<uint2*>(&dh[i]) = *reinterpret_cast<uint2*>(h);
}

__global__ __launch_bounds__(256) void wtrans_kernel(
    const float* __restrict__ w0, const float* __restrict__ w1,
    const float* __restrict__ w2, const float* __restrict__ w3) {
    const float* W = blockIdx.z == 0 ? w0 : blockIdx.z == 1 ? w1 : blockIdx.z == 2 ? w2 : w3;
    ushortT* Th = g_wh + (size_t)blockIdx.z * Ddim * Ddim;
    __shared__ float tile[32][33];
    const int n0 = blockIdx.x * 32, k0 = blockIdx.y * 32;
    const int tx = threadIdx.x & 31, ty = threadIdx.x >> 5;
#pragma unroll
    for (int r = 0; r < 4; ++r)
        tile[ty + r * 8][tx] = W[(size_t)(k0 + ty + r * 8) * Ddim + n0 + tx];
    __syncthreads();
#pragma unroll
    for (int r = 0; r < 4; ++r) {
        float v = tile[tx][ty + r * 8];
        Th[(size_t)(n0 + ty + r * 8) * Ddim + k0 + tx] =
            __half_as_ushort(__float2half_rn(v));
    }
}

__global__ __launch_bounds__(256) void vtrans_kernel() {
    const int bh = blockIdx.z, b = bh >> 4, h = bh & 15;
    const int s0 = blockIdx.x * 32, d0 = blockIdx.y * 32;
    __shared__ ushortT th[32][34];
    const int tx = threadIdx.x & 31, ty = threadIdx.x >> 5;
    const ushortT* vh = g_qkvh + 2 * PLANE;
#pragma unroll
    for (int r = 0; r < 4; ++r) {
        size_t src = (size_t)(b * Sdim + s0 + ty + r * 8) * Ddim + h * DHdim + d0 + tx;
        th[ty + r * 8][tx] = vh[src];
    }
    __syncthreads();
#pragma unroll
    for (int r = 0; r < 4; ++r) {
        size_t dst = ((size_t)bh * DHdim + d0 + ty + r * 8) * Sdim + s0 + tx;
        g_vth[dst] = th[tx][ty + r * 8];
    }
}

__global__ __launch_bounds__(256) void rowsum_kernel() {
    const int idx = blockIdx.x * 256 + threadIdx.x;
    float s = 0.0f;
#pragma unroll
    for (int i = 0; i < 16; ++i) s += g_part[(size_t)idx * 16 + i];
    g_inv[idx] = 1.0f / s;
}

// ---------------------------------------------------------------------------
// fp16-split tensor-core GEMM. BM=128 fixed. B always hi-plane only.
// APASS: 2 = A split h+l (2 MMA passes); 1 = A hi only (1 pass).
// ASRC:  0 = fp16 planes via cp.async
//        2 = ctx: A = fp16 exp scratch; scale by g_inv, write fp32 attn out,
//            scaled fp16 into smem (double-buffered), 1 MMA pass. BK=32 ONLY
//            (EPT=16 fits in regs; BK=64 spills — measured R14 regression).
// EPI:   0 = +bias -> hi plane; 1 = exp/mask (fp16-rounded) -> exp plane +
//        row partial sums of the ROUNDED values; 2 = split h+l planes;
//        3 = +bias -> fp32
// ---------------------------------------------------------------------------
template <int BN, int BKt, int STAGES, int ASRC, int EPI, int APASS>
__global__ __launch_bounds__(256, 2) void mm_kernel(
    const ushortT* __restrict__ Ahp, const ushortT* __restrict__ Alp,
    float* __restrict__ Awb,
    const ushortT* __restrict__ Bhp,
    float* __restrict__ Cf, ushortT* __restrict__ Ch, ushortT* __restrict__ Cl,
    const float* __restrict__ bias,
    int nt, int lda, int ldb, int ldc,
    long sbA, long shA, long sbB, long shB, long sbC, long shC, long sBias) {
    constexpr int KP  = BKt + 8;
    constexpr int APB = 128 * KP * 2;
    constexpr int BPB = BN * KP * 2;
    constexpr int ABUF = 2;
    constexpr int CPR = BKt / 8;
    constexpr int ACH = CPR / 2;
    constexpr int BCH = BN * CPR / 256;
    constexpr int KS  = BKt / 16;
    constexpr int NW  = BN / 32;
    constexpr int N8  = BN / 16;
    constexpr int oAl = ABUF * APB;              // lo buffers (only if APASS==2)
    constexpr int oBh = APASS * ABUF * APB;
    constexpr int WAITN = (STAGES >= 2) ? STAGES - 2 : 0;

    extern __shared__ char smem[];
    const unsigned sbase = (unsigned)__cvta_generic_to_shared(smem);
    float* rsum2 = (float*)(smem + oBh + STAGES * BPB);

    const int t = threadIdx.x, lane = t & 31, warp = t >> 5;
    const int wm = (warp >> 1) * 32, wn = (warp & 1) * (BN / 2);
    const int z = blockIdx.z;
    const long aoff = (long)(z / Hdim) * sbA + (long)(z % Hdim) * shA;
    const long boff = (long)(z / Hdim) * sbB + (long)(z % Hdim) * shB;
    const long coff = (long)(z / Hdim) * sbC + (long)(z % Hdim) * shC;
    bias += (long)(z % Hdim) * sBias;
    const int row0 = blockIdx.y * 128, col0 = blockIdx.x * BN;
    const int lr = lane & 7, lhi = (lane >> 3) & 1, lk = lane >> 4;

    float acc[2][N8][4] = {};

    auto issueA = [&](int s, int kk) {
#pragma unroll
        for (int j = 0; j < ACH; ++j) {
            const int o = j * 256 + t, r = o / CPR, c = o % CPR;
            const unsigned d = sbase + s * APB + (unsigned)(r * KP + c * 8) * 2;
            const size_t g = aoff + (size_t)(row0 + r) * lda + kk + c * 8;
            cpasync16(d, &Ahp[g]);
            if (APASS == 2) cpasync16(d + oAl, &Alp[g]);
        }
    };
    auto issueB = [&](int s, int kk) {
#pragma unroll
        for (int j = 0; j < BCH; ++j) {
            const int o = j * 256 + t, r = o / CPR, c = o % CPR;
            const unsigned d = sbase + oBh + s * BPB + (unsigned)(r * KP + c * 8) * 2;
            const size_t g = boff + (size_t)(col0 + r) * ldb + kk + c * 8;
            cpasync16(d, &Bhp[g]);
        }
    };
    auto compute = [&](int sA, int sB) {
#pragma unroll
        for (int ks = 0; ks < KS; ++ks) {
            unsigned ah[2][4], al[2][4];
#pragma unroll
            for (int mi = 0; mi < 2; ++mi) {
                const unsigned ad = sbase + sA * APB +
                    (unsigned)((wm + mi * 16 + lr + lhi * 8) * KP + ks * 16 + lk * 8) * 2;
                ldmx4(ah[mi], ad);
                if (APASS == 2) ldmx4(al[mi], ad + oAl);
            }
#pragma unroll
            for (int ni = 0; ni < NW; ++ni) {
                const unsigned bd = sbase + oBh + sB * BPB +
                    (unsigned)((wn + ni * 16 + lr + lhi * 8) * KP + ks * 16 + lk * 8) * 2;
                unsigned rh[4];
                ldmx4(rh, bd);
#pragma unroll
                for (int mi = 0; mi < 2; ++mi) {
                    mma_f16(acc[mi][ni * 2],     ah[mi], rh[0], rh[2]);
                    mma_f16(acc[mi][ni * 2 + 1], ah[mi], rh[1], rh[3]);
                    if (APASS == 2) {
                        mma_f16(acc[mi][ni * 2],     al[mi], rh[0], rh[2]);
                        mma_f16(acc[mi][ni * 2 + 1], al[mi], rh[1], rh[3]);
                    }
                }
            }
        }
    };

    if (ASRC == 0) {
        if (STAGES == 1) {
            for (int i = 0; i < nt; ++i) {
                if (i > 0) __syncthreads();
                issueA(0, i * BKt); issueB(0, i * BKt); cpcommit();
                cpwait<0>();
                __syncthreads();
                compute(0, 0);
            }
        } else {
#pragma unroll 1
            for (int s = 0; s < STAGES - 1 && s < nt; ++s) {
                issueA(s, s * BKt); issueB(s, s * BKt); cpcommit();
            }
            for (int i = 0; i < nt; ++i) {
                cpwait<WAITN>();
                __syncthreads();
                const int nx = i + STAGES - 1;
                if (nx < nt) { issueA(nx % STAGES, nx * BKt); issueB(nx % STAGES, nx * BKt); }
                cpcommit();
                compute(i % STAGES, i % STAGES);
            }
        }
    } else {
        // ctx path (BK=32, EPT=16): A = fp16 exp scratch. Per tile: scale by
        // inv, write fp32 attn out, scaled fp16 into double-buffered smem.
        const int ar = t >> 1, ac0 = (t & 1) * 16;
        const float invv = g_inv[(size_t)z * Sdim + row0 + ar];
        const size_t arow = aoff + (size_t)(row0 + ar) * lda;
        uint4 areg[2];
        areg[0] = *reinterpret_cast<const uint4*>(&Ahp[arow + ac0]);
        areg[1] = *reinterpret_cast<const uint4*>(&Ahp[arow + ac0 + 8]);
        issueB(0, 0); cpcommit();
        for (int i = 0; i < nt; ++i) {
            const int sA = i & 1;
            const size_t cbase = arow + (size_t)i * BKt + ac0;
            float fv[16];
            ushortT hs[16];
            const ushortT* ap = reinterpret_cast<const ushortT*>(areg);
#pragma unroll
            for (int j = 0; j < 16; ++j) {
                float e = __half2float(__ushort_as_half(ap[j])) * invv;
                fv[j] = e;
                hs[j] = __half_as_ushort(__float2half_rn(e));
            }
#pragma unroll
            for (int j4 = 0; j4 < 4; ++j4)
                *reinterpret_cast<float4*>(&Awb[cbase + j4 * 4]) =
                    make_float4(fv[j4 * 4], fv[j4 * 4 + 1], fv[j4 * 4 + 2], fv[j4 * 4 + 3]);
            const unsigned off = (unsigned)(sA * APB + (ar * KP + ac0) * 2);
            *reinterpret_cast<uint4*>(smem + off)      = *reinterpret_cast<uint4*>(&hs[0]);
            *reinterpret_cast<uint4*>(smem + off + 16) = *reinterpret_cast<uint4*>(&hs[8]);
            if (i + 1 < nt) {
                areg[0] = *reinterpret_cast<const uint4*>(&Ahp[arow + (size_t)(i + 1) * BKt + ac0]);
                areg[1] = *reinterpret_cast<const uint4*>(&Ahp[arow + (size_t)(i + 1) * BKt + ac0 + 8]);
            }
            cpwait<0>();      // B(i) arrived
            __syncthreads();  // A STS visible; everyone done with compute(i-1)
            if (i + 1 < nt) { issueB((i + 1) & 1, (i + 1) * BKt); cpcommit(); }
            compute(sA, i & 1);
        }
    }

    // ---- epilogue ----
    const int maskbase = (z / Hdim) * Sdim;
#pragma unroll
    for (int mi = 0; mi < 2; ++mi)
#pragma unroll
        for (int n8 = 0; n8 < N8; ++n8) {
            const int rl0 = wm + mi * 16 + (lane >> 2);
            const int cl0 = wn + n8 * 8 + (lane & 3) * 2;
#pragma unroll
            for (int hf = 0; hf < 2; ++hf) {
                const int r = row0 + rl0 + hf * 8;
                const int c = col0 + cl0;
                float v0 = acc[mi][n8][hf * 2], v1 = acc[mi][n8][hf * 2 + 1];
                if (EPI == 0 || EPI == 3) { v0 += bias[c]; v1 += bias[c + 1]; }
                const size_t ci = coff + (size_t)r * ldc + c;
                if (EPI == 1) {
                    v0 = g_mask[maskbase + c]     ? __expf(v0 * 0.125f) : 0.0f;
                    v1 = g_mask[maskbase + c + 1] ? __expf(v1 * 0.125f) : 0.0f;
                    ushortT h0 = __half_as_ushort(__float2half_rn(v0));
                    ushortT h1 = __half_as_ushort(__float2half_rn(v1));
                    v0 = __half2float(__ushort_as_half(h0));   // rounded values
                    v1 = __half2float(__ushort_as_half(h1));   // for exact rowsum
                    acc[mi][n8][hf * 2] = v0; acc[mi][n8][hf * 2 + 1] = v1;
                    *reinterpret_cast<unsigned*>(&Ch[ci]) = (unsigned)h0 | ((unsigned)h1 << 16);
                } else if (EPI == 3) {
                    *reinterpret_cast<float2*>(&Cf[ci]) = make_float2(v0, v1);
                } else if (EPI == 0) {
                    ushortT h0 = __half_as_ushort(__float2half_rn(v0));
                    ushortT h1 = __half_as_ushort(__float2half_rn(v1));
                    *reinterpret_cast<unsigned*>(&Ch[ci]) = (unsigned)h0 | ((unsigned)h1 << 16);
                } else {  // EPI == 2: split planes for outproj
                    ushortT h0, l0, h1, l1;
                    split_hf(v0, h0, l0); split_hf(v1, h1, l1);
                    *reinterpret_cast<unsigned*>(&Ch[ci]) = (unsigned)h0 | ((unsigned)h1 << 16);
                    *reinterpret_cast<unsigned*>(&Cl[ci]) = (unsigned)l0 | ((unsigned)l1 << 16);
                }
            }
        }

    if (EPI == 1) {
#pragma unroll
        for (int mi = 0; mi < 2; ++mi)
#pragma unroll
            for (int hf = 0; hf < 2; ++hf) {
                float s = 0.0f;
#pragma unroll
                for (int n8 = 0; n8 < N8; ++n8)
                    s += acc[mi][n8][hf * 2] + acc[mi][n8][hf * 2 + 1];
                s += __shfl_xor_sync(0xFFFFFFFFu, s, 1);
                s += __shfl_xor_sync(0xFFFFFFFFu, s, 2);
                if ((lane & 3) == 0)
                    rsum2[(warp & 1) * 128 + wm + mi * 16 + (lane >> 2) + hf * 8] = s;
            }
        __syncthreads();
        if (t < 128) {
            float s = rsum2[t] + rsum2[128 + t];
            g_part[((size_t)z * Sdim + row0 + t) * 16 + blockIdx.x] = s;
        }
    }
}

// ---------------------------------------------------------------------------
extern "C" void kernel_launch(void* const* d_in, const int* in_sizes, int n_in,
                              void* d_out, int out_size) {
    const float* qs = (const float*)d_in[0];
    const float* ks = (const float*)d_in[1];
    const float* vs = (const float*)d_in[2];
    const void*  mk = d_in[3];
    const float* Wq = (const float*)d_in[4];
    const float* bq = (const float*)d_in[5];
    const float* Wk = (const float*)d_in[6];
    const float* bk = (const float*)d_in[7];
    const float* Wv = (const float*)d_in[8];
    const float* bv = (const float*)d_in[9];
    const float* Wo = (const float*)d_in[10];
    const float* bo = (const float*)d_in[11];

    float* out  = (float*)d_out;
    float* attn = out + PLANE;  // (out, attn) concatenated

    ushortT *inh, *qkvh, *vth, *wh, *ch, *cl, *exph;
    float* dbias;
    cudaGetSymbolAddress((void**)&inh,  g_inh);
    cudaGetSymbolAddress((void**)&qkvh, g_qkvh);
    cudaGetSymbolAddress((void**)&vth,  g_vth);
    cudaGetSymbolAddress((void**)&wh,   g_wh);
    cudaGetSymbolAddress((void**)&ch,   g_ch);   cudaGetSymbolAddress((void**)&cl,   g_cl);
    cudaGetSymbolAddress((void**)&exph, g_exph);
    cudaGetSymbolAddress((void**)&dbias, g_bias);

    const long SS = (long)Sdim * Sdim;
    const long SD = (long)Sdim * Ddim;
    const size_t WSZ = (size_t)Ddim * Ddim;
    dim3 blk(256);

    // smem: APASS*ABUF*APB + STAGES*BPB (+1024 rsum when EPI==1)
    const int SM_QKV  = 2 * (128 * 72 * 2) + 2 * (128 * 72 * 2);           // 73728 (BK=64)
    const int SM_SC   = 2 * (128 * 72 * 2) + 1 * (128 * 72 * 2) + 1024;    // 56320
    const int SM_CTX  = 2 * (128 * 40 * 2) + 2 * (64 * 40 * 2);            // 30720 (BK=32)
    const int SM_OUT  = 4 * (128 * 40 * 2) + 2 * (128 * 40 * 2);           // 61440 (BK=32)
    cudaFuncSetAttribute(mm_kernel<128, 64, 2, 0, 0, 1>, cudaFuncAttributeMaxDynamicSharedMemorySize, SM_QKV);
    cudaFuncSetAttribute(mm_kernel<128, 64, 1, 0, 1, 1>, cudaFuncAttributeMaxDynamicSharedMemorySize, SM_SC);
    cudaFuncSetAttribute(mm_kernel<64, 32, 2, 2, 2, 1>,  cudaFuncAttributeMaxDynamicSharedMemorySize, SM_CTX);
    cudaFuncSetAttribute(mm_kernel<128, 32, 2, 0, 3, 2>, cudaFuncAttributeMaxDynamicSharedMemorySize, SM_OUT);

    mask_expand_kernel<<<1, 256>>>(mk, bq, bk, bv);
    split_inputs_kernel<<<dim3(4096, 1, 3), blk>>>(qs, ks, vs);
    wtrans_kernel<<<dim3(32, 32, 4), blk>>>(Wq, Wk, Wv, Wo);

    // Fused QKV projections (1-pass, BK=64) -> q/k/v hi planes
    dim3 gqkv(Ddim / 128, NROWS / 128, 3);  // (8, 32, 3)
    mm_kernel<128, 64, 2, 0, 0, 1><<<gqkv, blk, SM_QKV>>>(
        inh, nullptr, nullptr, wh,
        nullptr, qkvh, nullptr, dbias, 16, Ddim, Ddim, Ddim,
        0, (long)PLANE, 0, (long)WSZ, 0, (long)PLANE, Ddim);

    vtrans_kernel<<<dim3(Sdim / 32, DHdim / 32, 32), blk>>>();

    // scores (1-pass) -> fp16 exp scratch + row partial sums of rounded exps
    dim3 gsc(Sdim / 128, Sdim / 128, Bdim * Hdim);  // (16, 16, 32)
    mm_kernel<128, 64, 1, 0, 1, 1><<<gsc, blk, SM_SC>>>(
        qkvh, nullptr, nullptr, qkvh + PLANE,
        nullptr, exph, nullptr, nullptr,
        1, Ddim, Ddim, Sdim, SD, DHdim, SD, DHdim, 16 * SS, SS, 0);

    rowsum_kernel<<<NROWS_A / 256, 256>>>();

    // ctx (1-pass, BK=32, A=fp16 exp scratch): fp32 attn out + ctx planes
    dim3 gctx(1, Sdim / 128, Bdim * Hdim);  // (1, 16, 32)
    mm_kernel<64, 32, 2, 2, 2, 1><<<gctx, blk, SM_CTX>>>(
        exph, nullptr, attn, vth, nullptr, ch, cl, nullptr,
        64, Sdim, Sdim, Ddim,
        16 * SS, SS, (long)16 * DHdim * Sdim, (long)DHdim * Sdim, SD, DHdim, 0);

    // output projection (A=ctx split 2-pass, BK=32) -> fp32 out
    dim3 gproj(Ddim / 128, NROWS / 128, 1);  // (8, 32)
    mm_kernel<128, 32, 2, 0, 3, 2><<<gproj, blk, SM_OUT>>>(
        ch, cl, nullptr, wh + 3 * WSZ,
        out, nullptr, nullptr, bo, 32, Ddim, Ddim, Ddim, 0, 0, 0, 0, 0, 0, 0);
}